// round 2
// baseline (speedup 1.0000x reference)
#include <cuda_runtime.h>
#include <cuda_bf16.h>
#include <math.h>

#define HDIM 256
#define BSEG 4096
#define K1   (3 * HDIM)   // 768

// Scratch (device globals — no allocation allowed)
__device__ float g_combined[BSEG * K1];    // [B, 3H] = mean | sum | max
__device__ float g_hidden[BSEG * HDIM];    // [B, H]

// ---------------------------------------------------------------------------
// Stage 1: segment pooling. batch is sorted (int32 — JAX x64 disabled
// downcasts the declared int64), so block b binary-searches its [start, end)
// row range and reduces columns with one thread per column.
// ---------------------------------------------------------------------------
__device__ __forceinline__ int lower_bound_i32(const int* __restrict__ a,
                                               int n, int v) {
    int lo = 0, hi = n;
    while (lo < hi) {
        int mid = (lo + hi) >> 1;
        if (a[mid] < v) lo = mid + 1; else hi = mid;
    }
    return lo;
}

__global__ void __launch_bounds__(HDIM)
pool_kernel(const float* __restrict__ feat,
            const int* __restrict__ batch,
            float* __restrict__ combined, int n_rows) {
    const int b = blockIdx.x;
    const int t = threadIdx.x;

    __shared__ int s_start, s_end;
    if (t == 0) {
        s_start = lower_bound_i32(batch, n_rows, b);
        s_end   = lower_bound_i32(batch, n_rows, b + 1);
    }
    __syncthreads();
    const int start = s_start;
    const int end   = s_end;
    const int cnt   = end - start;

    float s0 = 0.f, s1 = 0.f, s2 = 0.f, s3 = 0.f;
    float m0 = -INFINITY, m1 = -INFINITY, m2 = -INFINITY, m3 = -INFINITY;

    int i = start;
    for (; i + 3 < end; i += 4) {
        float v0 = feat[(size_t)(i + 0) * HDIM + t];
        float v1 = feat[(size_t)(i + 1) * HDIM + t];
        float v2 = feat[(size_t)(i + 2) * HDIM + t];
        float v3 = feat[(size_t)(i + 3) * HDIM + t];
        s0 += v0; s1 += v1; s2 += v2; s3 += v3;
        m0 = fmaxf(m0, v0); m1 = fmaxf(m1, v1);
        m2 = fmaxf(m2, v2); m3 = fmaxf(m3, v3);
    }
    for (; i < end; ++i) {
        float v = feat[(size_t)i * HDIM + t];
        s0 += v; m0 = fmaxf(m0, v);
    }
    float sum = (s0 + s1) + (s2 + s3);
    float mx  = fmaxf(fmaxf(m0, m1), fmaxf(m2, m3));

    float mean = sum / fmaxf((float)cnt, 1.0f);
    if (cnt == 0) { mx = 0.f; sum = 0.f; mean = 0.f; }

    float* row = combined + (size_t)b * K1;
    row[t]            = mean;
    row[HDIM + t]     = sum;
    row[2 * HDIM + t] = mx;
}

// ---------------------------------------------------------------------------
// Stage 2/3: SMEM-tiled fp32 GEMM  C[M,N] = act(A[M,K] @ W[K,N] + bias)
// BM=BN=64, BK=32, 256 threads, 4x4 microtile. M,N,K multiples of tile sizes.
// ---------------------------------------------------------------------------
__global__ void __launch_bounds__(256)
gemm_bias_act(const float* __restrict__ A,
              const float* __restrict__ W,
              const float* __restrict__ bias,
              float* __restrict__ C,
              int M, int K, int N, int do_silu) {
    __shared__ float As[32][65];  // [k][m], padded
    __shared__ float Bs[32][64];  // [k][n]

    const int tid = threadIdx.x;
    const int tx  = tid & 15;       // 0..15 -> n
    const int ty  = tid >> 4;       // 0..15 -> m
    const int bm  = blockIdx.y * 64;
    const int bn  = blockIdx.x * 64;

    float acc[4][4] = {};

    for (int k0 = 0; k0 < K; k0 += 32) {
        // load A tile 64x32 (transposed into As[k][m])
        #pragma unroll
        for (int l = tid; l < 64 * 32; l += 256) {
            int r = l >> 5;       // 0..63 (m)
            int c = l & 31;       // 0..31 (k)
            As[c][r] = A[(size_t)(bm + r) * K + k0 + c];
        }
        // load W tile 32x64
        #pragma unroll
        for (int l = tid; l < 32 * 64; l += 256) {
            int r = l >> 6;       // 0..31 (k)
            int j = l & 63;       // 0..63 (n)
            Bs[r][j] = W[(size_t)(k0 + r) * N + bn + j];
        }
        __syncthreads();

        #pragma unroll
        for (int k = 0; k < 32; ++k) {
            float a[4], bv[4];
            #pragma unroll
            for (int u = 0; u < 4; ++u) a[u]  = As[k][ty * 4 + u];
            #pragma unroll
            for (int u = 0; u < 4; ++u) bv[u] = Bs[k][tx * 4 + u];
            #pragma unroll
            for (int iu = 0; iu < 4; ++iu)
                #pragma unroll
                for (int ju = 0; ju < 4; ++ju)
                    acc[iu][ju] += a[iu] * bv[ju];
        }
        __syncthreads();
    }

    #pragma unroll
    for (int iu = 0; iu < 4; ++iu) {
        int m = bm + ty * 4 + iu;
        #pragma unroll
        for (int ju = 0; ju < 4; ++ju) {
            int n = bn + tx * 4 + ju;
            float v = acc[iu][ju] + bias[n];
            if (do_silu) v = v / (1.0f + expf(-v));
            C[(size_t)m * N + n] = v;
        }
    }
}

// ---------------------------------------------------------------------------
extern "C" void kernel_launch(void* const* d_in, const int* in_sizes, int n_in,
                              void* d_out, int out_size) {
    const float* feat  = (const float*)d_in[0];      // [N, 256] f32
    const int*   batch = (const int*)d_in[1];        // [N] i32 sorted
    const float* W1    = (const float*)d_in[2];      // [768, 256]
    const float* b1    = (const float*)d_in[3];      // [256]
    const float* W2    = (const float*)d_in[4];      // [256, 256]
    const float* b2    = (const float*)d_in[5];      // [256]
    float*       out   = (float*)d_out;              // [4096, 256]

    const int n_rows = in_sizes[1];

    float* combined;
    float* hidden;
    cudaGetSymbolAddress((void**)&combined, g_combined);
    cudaGetSymbolAddress((void**)&hidden,   g_hidden);

    pool_kernel<<<BSEG, HDIM>>>(feat, batch, combined, n_rows);

    dim3 g1(HDIM / 64, BSEG / 64);   // (4, 64)
    gemm_bias_act<<<g1, 256>>>(combined, W1, b1, hidden, BSEG, K1, HDIM, 1);

    dim3 g2(HDIM / 64, BSEG / 64);
    gemm_bias_act<<<g2, 256>>>(hidden, W2, b2, out, BSEG, HDIM, HDIM, 0);
}

// round 3
// speedup vs baseline: 1.0839x; 1.0839x over previous
#include <cuda_runtime.h>
#include <cuda_bf16.h>
#include <math.h>

#define HDIM 256
#define BSEG 4096
#define K1   (3 * HDIM)   // 768

__device__ float g_combined[BSEG * K1];    // [B, 3H] = mean | sum | max
__device__ float g_hidden[BSEG * HDIM];    // [B, H]

__device__ __forceinline__ int lower_bound_i32(const int* __restrict__ a,
                                               int n, int v) {
    int lo = 0, hi = n;
    while (lo < hi) {
        int mid = (lo + hi) >> 1;
        if (a[mid] < v) lo = mid + 1; else hi = mid;
    }
    return lo;
}

// ---------------------------------------------------------------------------
// Stage 1: segment pooling with float4 loads.
// 256 threads = 4 row-groups x 64 lanes. Lane c covers columns [4c, 4c+4).
// Group g covers rows start+g, start+g+4, ... (2 rows in flight per thread).
// Cross-group reduction via smem at the end.
// ---------------------------------------------------------------------------
__global__ void __launch_bounds__(256)
pool_kernel(const float4* __restrict__ feat4,   // [N, 64] float4
            const int* __restrict__ batch,
            float4* __restrict__ combined4,     // [B, 192] float4 (mean|sum|max)
            int n_rows) {
    const int b = blockIdx.x;
    const int t = threadIdx.x;
    const int g = t >> 6;   // 0..3
    const int c = t & 63;   // 0..63

    __shared__ int s_se[2];
    if (t < 2) s_se[t] = lower_bound_i32(batch, n_rows, b + t);
    __syncthreads();
    const int start = s_se[0];
    const int end   = s_se[1];
    const int cnt   = end - start;

    float4 s0 = make_float4(0.f, 0.f, 0.f, 0.f);
    float4 s1 = make_float4(0.f, 0.f, 0.f, 0.f);
    float4 m0 = make_float4(-INFINITY, -INFINITY, -INFINITY, -INFINITY);
    float4 m1 = m0;

    int i = start + g;
    for (; i + 4 < end; i += 8) {
        float4 v0 = feat4[(size_t)i * 64 + c];
        float4 v1 = feat4[(size_t)(i + 4) * 64 + c];
        s0.x += v0.x; s0.y += v0.y; s0.z += v0.z; s0.w += v0.w;
        s1.x += v1.x; s1.y += v1.y; s1.z += v1.z; s1.w += v1.w;
        m0.x = fmaxf(m0.x, v0.x); m0.y = fmaxf(m0.y, v0.y);
        m0.z = fmaxf(m0.z, v0.z); m0.w = fmaxf(m0.w, v0.w);
        m1.x = fmaxf(m1.x, v1.x); m1.y = fmaxf(m1.y, v1.y);
        m1.z = fmaxf(m1.z, v1.z); m1.w = fmaxf(m1.w, v1.w);
    }
    if (i < end) {
        float4 v0 = feat4[(size_t)i * 64 + c];
        s0.x += v0.x; s0.y += v0.y; s0.z += v0.z; s0.w += v0.w;
        m0.x = fmaxf(m0.x, v0.x); m0.y = fmaxf(m0.y, v0.y);
        m0.z = fmaxf(m0.z, v0.z); m0.w = fmaxf(m0.w, v0.w);
    }
    float4 s = make_float4(s0.x + s1.x, s0.y + s1.y, s0.z + s1.z, s0.w + s1.w);
    float4 m = make_float4(fmaxf(m0.x, m1.x), fmaxf(m0.y, m1.y),
                           fmaxf(m0.z, m1.z), fmaxf(m0.w, m1.w));

    __shared__ float4 red_s[4][64];
    __shared__ float4 red_m[4][64];
    red_s[g][c] = s;
    red_m[g][c] = m;
    __syncthreads();

    if (t < 64) {
        float4 S = red_s[0][t], M = red_m[0][t];
        #pragma unroll
        for (int gg = 1; gg < 4; ++gg) {
            float4 ps = red_s[gg][t], pm = red_m[gg][t];
            S.x += ps.x; S.y += ps.y; S.z += ps.z; S.w += ps.w;
            M.x = fmaxf(M.x, pm.x); M.y = fmaxf(M.y, pm.y);
            M.z = fmaxf(M.z, pm.z); M.w = fmaxf(M.w, pm.w);
        }
        float inv = (cnt > 0) ? (1.0f / (float)cnt) : 0.0f;
        if (cnt == 0) {
            S = make_float4(0.f, 0.f, 0.f, 0.f);
            M = S;
        }
        float4 mean = make_float4(S.x * inv, S.y * inv, S.z * inv, S.w * inv);
        float4* row = combined4 + (size_t)b * 192;
        row[t]       = mean;
        row[64 + t]  = S;
        row[128 + t] = M;
    }
}

// ---------------------------------------------------------------------------
// Stage 2/3: double-buffered SMEM-tiled fp32 GEMM.
// C[M,N] = act(A[M,K] @ W[K,N] + bias). BM=BN=64, BK=32, 256 threads, 4x4.
// ---------------------------------------------------------------------------
__global__ void __launch_bounds__(256)
gemm_bias_act(const float* __restrict__ A,
              const float* __restrict__ W,
              const float* __restrict__ bias,
              float* __restrict__ C,
              int M, int K, int N, int do_silu) {
    __shared__ float As[2][32][68];  // [buf][k][m], stride 68 keeps m*4 16B-aligned
    __shared__ float Bs[2][32][64];  // [buf][k][n]

    const int tid = threadIdx.x;
    const int tx  = tid & 15;
    const int ty  = tid >> 4;
    const int bm  = blockIdx.y * 64;
    const int bn  = blockIdx.x * 64;

    // A tile loads: 64(m) x 32(k) = 512 float4; thread does l = tid, tid+256
    const int la0_r = tid >> 3, la0_c = (tid & 7) * 4;            // m, k-offset
    const int la1_r = (tid + 256) >> 3, la1_c = ((tid + 256) & 7) * 4;
    // W tile loads: 32(k) x 64(n) = 512 float4
    const int lb0_r = tid >> 4, lb0_n = (tid & 15) * 4;           // k, n-offset
    const int lb1_r = (tid + 256) >> 4, lb1_n = ((tid + 256) & 15) * 4;

    const int nk = K >> 5;
    float4 a0, a1, w0, w1;

    // prologue: load tile 0
    a0 = *(const float4*)&A[(size_t)(bm + la0_r) * K + la0_c];
    a1 = *(const float4*)&A[(size_t)(bm + la1_r) * K + la1_c];
    w0 = *(const float4*)&W[(size_t)lb0_r * N + bn + lb0_n];
    w1 = *(const float4*)&W[(size_t)lb1_r * N + bn + lb1_n];

    As[0][la0_c + 0][la0_r] = a0.x; As[0][la0_c + 1][la0_r] = a0.y;
    As[0][la0_c + 2][la0_r] = a0.z; As[0][la0_c + 3][la0_r] = a0.w;
    As[0][la1_c + 0][la1_r] = a1.x; As[0][la1_c + 1][la1_r] = a1.y;
    As[0][la1_c + 2][la1_r] = a1.z; As[0][la1_c + 3][la1_r] = a1.w;
    *(float4*)&Bs[0][lb0_r][lb0_n] = w0;
    *(float4*)&Bs[0][lb1_r][lb1_n] = w1;
    __syncthreads();

    float acc[4][4] = {};

    for (int kk = 0; kk < nk; ++kk) {
        const int buf = kk & 1;
        if (kk + 1 < nk) {
            const int k0 = (kk + 1) << 5;
            a0 = *(const float4*)&A[(size_t)(bm + la0_r) * K + k0 + la0_c];
            a1 = *(const float4*)&A[(size_t)(bm + la1_r) * K + k0 + la1_c];
            w0 = *(const float4*)&W[(size_t)(k0 + lb0_r) * N + bn + lb0_n];
            w1 = *(const float4*)&W[(size_t)(k0 + lb1_r) * N + bn + lb1_n];
        }

        #pragma unroll
        for (int k = 0; k < 32; ++k) {
            float4 av = *(const float4*)&As[buf][k][ty * 4];
            float4 bv = *(const float4*)&Bs[buf][k][tx * 4];
            float a[4] = {av.x, av.y, av.z, av.w};
            float bb[4] = {bv.x, bv.y, bv.z, bv.w};
            #pragma unroll
            for (int iu = 0; iu < 4; ++iu)
                #pragma unroll
                for (int ju = 0; ju < 4; ++ju)
                    acc[iu][ju] += a[iu] * bb[ju];
        }

        if (kk + 1 < nk) {
            const int nb = buf ^ 1;
            As[nb][la0_c + 0][la0_r] = a0.x; As[nb][la0_c + 1][la0_r] = a0.y;
            As[nb][la0_c + 2][la0_r] = a0.z; As[nb][la0_c + 3][la0_r] = a0.w;
            As[nb][la1_c + 0][la1_r] = a1.x; As[nb][la1_c + 1][la1_r] = a1.y;
            As[nb][la1_c + 2][la1_r] = a1.z; As[nb][la1_c + 3][la1_r] = a1.w;
            *(float4*)&Bs[nb][lb0_r][lb0_n] = w0;
            *(float4*)&Bs[nb][lb1_r][lb1_n] = w1;
            __syncthreads();
        }
    }

    #pragma unroll
    for (int iu = 0; iu < 4; ++iu) {
        const int m = bm + ty * 4 + iu;
        float4 v;
        float* vp = &v.x;
        #pragma unroll
        for (int ju = 0; ju < 4; ++ju) {
            const int n = bn + tx * 4 + ju;
            float x = acc[iu][ju] + bias[n];
            if (do_silu) x = x / (1.0f + __expf(-x));
            vp[ju] = x;
        }
        *(float4*)&C[(size_t)m * N + bn + tx * 4 - bn + (size_t)0 + ( (size_t)bn )] = v; // placeholder removed below
    }
}

// NOTE: the store line above is wrong on purpose? No — fix: see corrected kernel below.

// ---------------------------------------------------------------------------
extern "C" void kernel_launch(void* const* d_in, const int* in_sizes, int n_in,
                              void* d_out, int out_size);

// Corrected epilogue version (the one actually used):
__global__ void __launch_bounds__(256)
gemm_bias_act_v2(const float* __restrict__ A,
                 const float* __restrict__ W,
                 const float* __restrict__ bias,
                 float* __restrict__ C,
                 int M, int K, int N, int do_silu) {
    __shared__ float As[2][32][68];
    __shared__ float Bs[2][32][64];

    const int tid = threadIdx.x;
    const int tx  = tid & 15;
    const int ty  = tid >> 4;
    const int bm  = blockIdx.y * 64;
    const int bn  = blockIdx.x * 64;

    const int la0_r = tid >> 3, la0_c = (tid & 7) * 4;
    const int la1_r = (tid + 256) >> 3, la1_c = ((tid + 256) & 7) * 4;
    const int lb0_r = tid >> 4, lb0_n = (tid & 15) * 4;
    const int lb1_r = (tid + 256) >> 4, lb1_n = ((tid + 256) & 15) * 4;

    const int nk = K >> 5;
    float4 a0, a1, w0, w1;

    a0 = *(const float4*)&A[(size_t)(bm + la0_r) * K + la0_c];
    a1 = *(const float4*)&A[(size_t)(bm + la1_r) * K + la1_c];
    w0 = *(const float4*)&W[(size_t)lb0_r * N + bn + lb0_n];
    w1 = *(const float4*)&W[(size_t)lb1_r * N + bn + lb1_n];

    As[0][la0_c + 0][la0_r] = a0.x; As[0][la0_c + 1][la0_r] = a0.y;
    As[0][la0_c + 2][la0_r] = a0.z; As[0][la0_c + 3][la0_r] = a0.w;
    As[0][la1_c + 0][la1_r] = a1.x; As[0][la1_c + 1][la1_r] = a1.y;
    As[0][la1_c + 2][la1_r] = a1.z; As[0][la1_c + 3][la1_r] = a1.w;
    *(float4*)&Bs[0][lb0_r][lb0_n] = w0;
    *(float4*)&Bs[0][lb1_r][lb1_n] = w1;
    __syncthreads();

    float acc[4][4] = {};

    for (int kk = 0; kk < nk; ++kk) {
        const int buf = kk & 1;
        if (kk + 1 < nk) {
            const int k0 = (kk + 1) << 5;
            a0 = *(const float4*)&A[(size_t)(bm + la0_r) * K + k0 + la0_c];
            a1 = *(const float4*)&A[(size_t)(bm + la1_r) * K + k0 + la1_c];
            w0 = *(const float4*)&W[(size_t)(k0 + lb0_r) * N + bn + lb0_n];
            w1 = *(const float4*)&W[(size_t)(k0 + lb1_r) * N + bn + lb1_n];
        }

        #pragma unroll
        for (int k = 0; k < 32; ++k) {
            float4 av = *(const float4*)&As[buf][k][ty * 4];
            float4 bv = *(const float4*)&Bs[buf][k][tx * 4];
            float a[4] = {av.x, av.y, av.z, av.w};
            float bb[4] = {bv.x, bv.y, bv.z, bv.w};
            #pragma unroll
            for (int iu = 0; iu < 4; ++iu)
                #pragma unroll
                for (int ju = 0; ju < 4; ++ju)
                    acc[iu][ju] += a[iu] * bb[ju];
        }

        if (kk + 1 < nk) {
            const int nb = buf ^ 1;
            As[nb][la0_c + 0][la0_r] = a0.x; As[nb][la0_c + 1][la0_r] = a0.y;
            As[nb][la0_c + 2][la0_r] = a0.z; As[nb][la0_c + 3][la0_r] = a0.w;
            As[nb][la1_c + 0][la1_r] = a1.x; As[nb][la1_c + 1][la1_r] = a1.y;
            As[nb][la1_c + 2][la1_r] = a1.z; As[nb][la1_c + 3][la1_r] = a1.w;
            *(float4*)&Bs[nb][lb0_r][lb0_n] = w0;
            *(float4*)&Bs[nb][lb1_r][lb1_n] = w1;
            __syncthreads();
        }
    }

    const float4 bv4 = *(const float4*)&bias[bn + tx * 4];
    const float bb[4] = {bv4.x, bv4.y, bv4.z, bv4.w};
    #pragma unroll
    for (int iu = 0; iu < 4; ++iu) {
        const int m = bm + ty * 4 + iu;
        float4 v;
        float x0 = acc[iu][0] + bb[0];
        float x1 = acc[iu][1] + bb[1];
        float x2 = acc[iu][2] + bb[2];
        float x3 = acc[iu][3] + bb[3];
        if (do_silu) {
            x0 = x0 / (1.0f + __expf(-x0));
            x1 = x1 / (1.0f + __expf(-x1));
            x2 = x2 / (1.0f + __expf(-x2));
            x3 = x3 / (1.0f + __expf(-x3));
        }
        v = make_float4(x0, x1, x2, x3);
        *(float4*)&C[(size_t)m * N + bn + tx * 4] = v;
    }
}

// ---------------------------------------------------------------------------
extern "C" void kernel_launch(void* const* d_in, const int* in_sizes, int n_in,
                              void* d_out, int out_size) {
    const float* feat  = (const float*)d_in[0];
    const int*   batch = (const int*)d_in[1];
    const float* W1    = (const float*)d_in[2];
    const float* b1    = (const float*)d_in[3];
    const float* W2    = (const float*)d_in[4];
    const float* b2    = (const float*)d_in[5];
    float*       out   = (float*)d_out;

    const int n_rows = in_sizes[1];

    float* combined;
    float* hidden;
    cudaGetSymbolAddress((void**)&combined, g_combined);
    cudaGetSymbolAddress((void**)&hidden,   g_hidden);

    pool_kernel<<<BSEG, 256>>>((const float4*)feat, batch,
                               (float4*)combined, n_rows);

    dim3 g1(HDIM / 64, BSEG / 64);
    gemm_bias_act_v2<<<g1, 256>>>(combined, W1, b1, hidden, BSEG, K1, HDIM, 1);

    dim3 g2(HDIM / 64, BSEG / 64);
    gemm_bias_act_v2<<<g2, 256>>>(hidden, W2, b2, out, BSEG, HDIM, HDIM, 0);
}